// round 1
// baseline (speedup 1.0000x reference)
#include <cuda_runtime.h>
#include <cuda_bf16.h>
#include <mma.h>

using namespace nvcuda;

namespace {
constexpr int B_ = 8, V_ = 64, T_ = 256, T1_ = 257, D_ = 256, H_ = 8, DH_ = 32;
constexpr float EPS = 1e-5f;
constexpr int LDA = 264;                         // bf16 elems per smem row (pad 8)
constexpr int SM_XN = 0;
constexpr int SM_V  = V_ * LDA * 2;              // 33792
constexpr int SM_C  = SM_V + V_ * LDA * 2;       // 67584
constexpr int SM_W  = SM_C + V_ * D_ * 4;        // 133120
constexpr int SM_TOTAL = SM_W + D_ * 16 * 2;     // 141312 bytes
}

// ---------------- scratch (device globals; no allocation allowed) -----------
__device__ float g_xbar[B_ * V_ * D_];
__device__ float g_q[B_ * V_ * D_];
__device__ float g_kk[B_ * V_ * D_];
__device__ __nv_bfloat16 g_attn[B_ * H_ * V_ * V_];
__device__ __nv_bfloat16 g_wv[D_ * D_];   // rows 512..767 of w_qkv (V proj)
__device__ __nv_bfloat16 g_wp[D_ * D_];   // w_proj
__device__ int g_mask_mode;               // 0 = int8, 1 = int32, 2 = float32

__device__ __forceinline__ float warp_sum(float v) {
#pragma unroll
    for (int o = 16; o; o >>= 1) v += __shfl_xor_sync(0xffffffffu, v, o);
    return v;
}

__device__ __forceinline__ bool mask_at(const void* m, int mode, long i) {
    if (mode == 0) return ((const unsigned char*)m)[i] != 0;
    if (mode == 1) return ((const int*)m)[i] != 0;
    return ((const float*)m)[i] != 0.0f;
}

// ---------------- K0: detect obs_mask storage layout ------------------------
// Scan the first 131072 BYTES (safe under every candidate layout: that is the
// full buffer if int8, the first quarter if int32/f32). Words all in {0,1}
// => int32. Words all in {0, 0x3F800000} => float32. Otherwise bytes (int8).
__global__ void k_detect(const unsigned char* m) {
    __shared__ int bad_i32, bad_f32;
    if (threadIdx.x == 0) { bad_i32 = 0; bad_f32 = 0; }
    __syncthreads();
    const unsigned int* w = (const unsigned int*)m;
    int bi = 0, bf = 0;
    for (int i = threadIdx.x; i < (B_ * V_ * T_) / 4; i += blockDim.x) {
        unsigned int x = w[i];
        if (x > 1u) bi = 1;
        if (x != 0u && x != 0x3F800000u) bf = 1;
    }
    if (bi) atomicOr(&bad_i32, 1);
    if (bf) atomicOr(&bad_f32, 1);
    __syncthreads();
    if (threadIdx.x == 0)
        g_mask_mode = (!bad_i32) ? 1 : ((!bad_f32) ? 2 : 0);
}

// ---------------- K1: convert Wv and Wproj to bf16 --------------------------
__global__ void k_convert(const float* __restrict__ wqkv, const float* __restrict__ wproj) {
    int i = blockIdx.x * blockDim.x + threadIdx.x;   // 65536 threads total
    g_wv[i] = __float2bfloat16(wqkv[512 * 256 + i]);
    g_wp[i] = __float2bfloat16(wproj[i]);
}

// ---------------- K2: xbar = masked mean over t of LayerNorm(x) -------------
// One block per (b,v). 8 warps; warp w owns rows t = w, w+8, ...
__global__ void k_xbar(const float* __restrict__ x, const void* __restrict__ mask,
                       const float* __restrict__ lnw, const float* __restrict__ lnb) {
    int bv = blockIdx.x;
    int w = threadIdx.x >> 5, lane = threadIdx.x & 31;
    int mode = g_mask_mode;

    float lw[8], lb[8], acc[8];
#pragma unroll
    for (int j = 0; j < 8; j++) {
        lw[j] = lnw[lane + 32 * j];
        lb[j] = lnb[lane + 32 * j];
        acc[j] = 0.0f;
    }
    float cnt = 0.0f;

    for (int t = w; t < T1_; t += 8) {
        const float* row = x + ((size_t)bv * T1_ + t) * D_;
        float r[8];
#pragma unroll
        for (int j = 0; j < 8; j++) r[j] = row[lane + 32 * j];
        float s = 0.0f;
#pragma unroll
        for (int j = 0; j < 8; j++) s += r[j];
        s = warp_sum(s);
        float mu = s * (1.0f / 256.0f);
        float v = 0.0f;
#pragma unroll
        for (int j = 0; j < 8; j++) { float d = r[j] - mu; v += d * d; }
        v = warp_sum(v);
        float rs = rsqrtf(v * (1.0f / 256.0f) + EPS);

        bool m = (t == 0) ? true : mask_at(mask, mode, (long)bv * T_ + (t - 1));
        if (m) {
#pragma unroll
            for (int j = 0; j < 8; j++)
                acc[j] += (r[j] - mu) * rs * lw[j] + lb[j];
            cnt += 1.0f;
        }
    }

    __shared__ float sAcc[8][256];
    __shared__ float sCnt[8];
#pragma unroll
    for (int j = 0; j < 8; j++) sAcc[w][lane + 32 * j] = acc[j];
    if (lane == 0) sCnt[w] = cnt;
    __syncthreads();

    int d = threadIdx.x;
    float tot = 0.0f, c = 0.0f;
#pragma unroll
    for (int i = 0; i < 8; i++) { tot += sAcc[i][d]; c += sCnt[i]; }
    c = fmaxf(c, 1.0f);
    g_xbar[bv * D_ + d] = tot / c;
}

// ---------------- K3: q = LN(x[:, :, 0]) @ Wq^T,  k = xbar @ Wk^T -----------
// One block per (b,v), 256 threads; thread e computes q[e], k[e].
__global__ void k_qk(const float* __restrict__ x, const float* __restrict__ lnw,
                     const float* __restrict__ lnb, const float* __restrict__ wqkv) {
    int bv = blockIdx.x;
    int tid = threadIdx.x;
    int w = tid >> 5, lane = tid & 31;
    __shared__ float xn0[256], xb[256];
    __shared__ float red[8];

    float v = x[(size_t)bv * T1_ * D_ + tid];   // t = 0 row
    float s = warp_sum(v);
    if (lane == 0) red[w] = s;
    __syncthreads();
    if (tid == 0) { float t = 0; for (int i = 0; i < 8; i++) t += red[i]; red[0] = t; }
    __syncthreads();
    float mu = red[0] * (1.0f / 256.0f);
    __syncthreads();

    float d0 = v - mu;
    float sq = warp_sum(d0 * d0);
    if (lane == 0) red[w] = sq;
    __syncthreads();
    if (tid == 0) { float t = 0; for (int i = 0; i < 8; i++) t += red[i]; red[0] = t; }
    __syncthreads();
    float rs = rsqrtf(red[0] * (1.0f / 256.0f) + EPS);

    xn0[tid] = d0 * rs * lnw[tid] + lnb[tid];
    xb[tid] = g_xbar[bv * D_ + tid];
    __syncthreads();

    const float* wq = wqkv + (size_t)tid * D_;          // Q rows 0..255
    const float* wk = wqkv + (size_t)(D_ + tid) * D_;   // K rows 256..511
    float q = 0.0f, k = 0.0f;
#pragma unroll 8
    for (int d = 0; d < D_; d++) { q += xn0[d] * wq[d]; k += xb[d] * wk[d]; }
    g_q[bv * D_ + tid] = q;
    g_kk[bv * D_ + tid] = k;
}

// ---------------- K4: attention softmax (per b,h: 64x64) --------------------
__global__ void k_attn() {
    int b = blockIdx.x / H_, h = blockIdx.x % H_;
    __shared__ float qh[64][32], kh[64][32], sc[64][64];
    int tid = threadIdx.x;   // 128 threads

    for (int i = tid; i < 64 * 32; i += 128) {
        int vq = i >> 5, d = i & 31;
        qh[vq][d] = g_q[(size_t)(b * 64 + vq) * D_ + h * 32 + d];
        kh[vq][d] = g_kk[(size_t)(b * 64 + vq) * D_ + h * 32 + d];
    }
    __syncthreads();

    const float scale = rsqrtf((float)DH_);
    for (int i = tid; i < 64 * 64; i += 128) {
        int vq = i >> 6, vk = i & 63;
        float s = 0.0f;
#pragma unroll
        for (int d = 0; d < 32; d++) s += qh[vq][d] * kh[vk][d];
        sc[vq][vk] = s * scale;
    }
    __syncthreads();

    if (tid < 64) {
        int vq = tid;
        float mx = -1e30f;
        for (int vk = 0; vk < 64; vk++) mx = fmaxf(mx, sc[vq][vk]);
        float sum = 0.0f;
        for (int vk = 0; vk < 64; vk++) { float e = expf(sc[vq][vk] - mx); sc[vq][vk] = e; sum += e; }
        float inv = 1.0f / sum;
        __nv_bfloat16* dst = g_attn + (size_t)((b * H_ + h) * 64 + vq) * 64;
        for (int vk = 0; vk < 64; vk++) dst[vk] = __float2bfloat16(sc[vq][vk] * inv);
    }
}

// ---------------- K5 helper: C(64x256) = A(64x256,bf16) @ W^T ---------------
// W streamed k-slab by k-slab through smem ([256 n][16 k] bf16).
__device__ __forceinline__ void gemm256(const __nv_bfloat16* __restrict__ Wg,
                                        const __nv_bfloat16* sA,
                                        __nv_bfloat16* sW, float* sC, int tid) {
    int w = tid >> 5, rt = w & 3, cg = w >> 2;
    wmma::fragment<wmma::accumulator, 16, 16, 16, float> acc[8];
#pragma unroll
    for (int j = 0; j < 8; j++) wmma::fill_fragment(acc[j], 0.0f);

    for (int ks = 0; ks < 16; ks++) {
        __syncthreads();
        // cooperative slab load: thread tid fetches W[tid][ks*16 .. +16)
        const uint4* s4 = (const uint4*)(Wg + (size_t)tid * D_ + ks * 16);
        uint4* d4 = (uint4*)(sW + tid * 16);
        d4[0] = s4[0];
        d4[1] = s4[1];
        __syncthreads();

        wmma::fragment<wmma::matrix_a, 16, 16, 16, __nv_bfloat16, wmma::row_major> af;
        wmma::load_matrix_sync(af, sA + (rt * 16) * LDA + ks * 16, LDA);
#pragma unroll
        for (int j = 0; j < 8; j++) {
            wmma::fragment<wmma::matrix_b, 16, 16, 16, __nv_bfloat16, wmma::col_major> bf;
            wmma::load_matrix_sync(bf, sW + (cg * 128 + j * 16) * 16, 16);
            wmma::mma_sync(acc[j], af, bf, acc[j]);
        }
    }
    __syncthreads();
#pragma unroll
    for (int j = 0; j < 8; j++)
        wmma::store_matrix_sync(sC + (rt * 16) * D_ + cg * 128 + j * 16, acc[j],
                                D_, wmma::mem_row_major);
}

// ---------------- K5: fused LN + V-GEMM + attn-mix + proj + residual --------
// One block per (b, t): 64 rows x 256 cols.
__global__ void k_main(const float* __restrict__ x, const float* __restrict__ lnw,
                       const float* __restrict__ lnb, const float* __restrict__ bproj,
                       float* __restrict__ out) {
    extern __shared__ char smem[];
    __nv_bfloat16* sXN = (__nv_bfloat16*)(smem + SM_XN);  // [64][LDA]
    __nv_bfloat16* sV  = (__nv_bfloat16*)(smem + SM_V);   // [64][LDA]
    float*         sC  = (float*)(smem + SM_C);           // [64][256]
    __nv_bfloat16* sW  = (__nv_bfloat16*)(smem + SM_W);   // [256][16]

    int b = blockIdx.x / T1_, t = blockIdx.x % T1_;
    int tid = threadIdx.x, w = tid >> 5, lane = tid & 31;
    int rt = w & 3, cg = w >> 2;

    // ---- LayerNorm of this (b, :, t, :) tile, written as bf16 ----
    for (int v = w; v < 64; v += 8) {
        const float* row = x + ((size_t)(b * 64 + v) * T1_ + t) * D_;
        float r[8];
#pragma unroll
        for (int j = 0; j < 8; j++) r[j] = row[lane + 32 * j];
        float s = 0.0f;
#pragma unroll
        for (int j = 0; j < 8; j++) s += r[j];
        s = warp_sum(s);
        float mu = s * (1.0f / 256.0f);
        float var = 0.0f;
#pragma unroll
        for (int j = 0; j < 8; j++) { float d = r[j] - mu; var += d * d; }
        var = warp_sum(var);
        float rs = rsqrtf(var * (1.0f / 256.0f) + EPS);
#pragma unroll
        for (int j = 0; j < 8; j++) {
            int d = lane + 32 * j;
            sXN[v * LDA + d] = __float2bfloat16((r[j] - mu) * rs * lnw[d] + lnb[d]);
        }
    }

    // ---- V projection: vf = xn @ Wv^T ----
    gemm256(g_wv, sXN, sW, sC, tid);
    __syncthreads();
    for (int i = tid; i < 64 * 256; i += 256) {
        int v = i >> 8, d = i & 255;
        sV[v * LDA + d] = __float2bfloat16(sC[i]);
    }
    __syncthreads();

    // ---- attention mixing (per head h: attn_h(64x64) @ vf_h(64x32)) ----
    for (int hh = 0; hh < 4; hh++) {
        int h = cg * 4 + hh;
        wmma::fragment<wmma::accumulator, 16, 16, 16, float> ac2[2];
        wmma::fill_fragment(ac2[0], 0.0f);
        wmma::fill_fragment(ac2[1], 0.0f);
#pragma unroll
        for (int kt = 0; kt < 4; kt++) {
            wmma::fragment<wmma::matrix_a, 16, 16, 16, __nv_bfloat16, wmma::row_major> af;
            wmma::load_matrix_sync(af,
                g_attn + (size_t)((b * H_ + h) * 64 + rt * 16) * 64 + kt * 16, 64);
#pragma unroll
            for (int j2 = 0; j2 < 2; j2++) {
                wmma::fragment<wmma::matrix_b, 16, 16, 16, __nv_bfloat16, wmma::row_major> bf;
                wmma::load_matrix_sync(bf, sV + (kt * 16) * LDA + h * 32 + j2 * 16, LDA);
                wmma::mma_sync(ac2[j2], af, bf, ac2[j2]);
            }
        }
        for (int j2 = 0; j2 < 2; j2++)
            wmma::store_matrix_sync(sC + (rt * 16) * D_ + h * 32 + j2 * 16, ac2[j2],
                                    D_, wmma::mem_row_major);
    }
    __syncthreads();
    for (int i = tid; i < 64 * 256; i += 256) {
        int v = i >> 8, d = i & 255;
        sXN[v * LDA + d] = __float2bfloat16(sC[i]);   // mixed -> reuse sXN
    }
    __syncthreads();

    // ---- output projection: mixed @ Wproj^T ----
    gemm256(g_wp, sXN, sW, sC, tid);
    __syncthreads();

    // ---- epilogue: out = x + (proj + b_proj) ----
    for (int i = tid; i < 64 * 256; i += 256) {
        int v = i >> 8, d = i & 255;
        size_t gi = ((size_t)(b * 64 + v) * T1_ + t) * D_ + d;
        out[gi] = sC[i] + bproj[d] + x[gi];
    }
}

// ---------------- launch ----------------------------------------------------
extern "C" void kernel_launch(void* const* d_in, const int* in_sizes, int n_in,
                              void* d_out, int out_size) {
    const float* x     = (const float*)d_in[0];
    const void*  mask  = d_in[1];
    const float* lnw   = (const float*)d_in[2];
    const float* lnb   = (const float*)d_in[3];
    const float* wqkv  = (const float*)d_in[4];
    const float* wproj = (const float*)d_in[5];
    const float* bproj = (const float*)d_in[6];
    float* out = (float*)d_out;

    cudaFuncSetAttribute(k_main, cudaFuncAttributeMaxDynamicSharedMemorySize, SM_TOTAL);

    k_detect<<<1, 256>>>((const unsigned char*)mask);
    k_convert<<<256, 256>>>(wqkv, wproj);
    k_xbar<<<B_ * V_, 256>>>(x, mask, lnw, lnb);
    k_qk<<<B_ * V_, 256>>>(x, lnw, lnb, wqkv);
    k_attn<<<B_ * H_, 128>>>();
    k_main<<<B_ * T1_, 256, SM_TOTAL>>>(x, lnw, lnb, bproj, out);
}

// round 2
// speedup vs baseline: 2.2062x; 2.2062x over previous
#include <cuda_runtime.h>
#include <cuda_bf16.h>
#include <mma.h>

using namespace nvcuda;

namespace {
constexpr int B_ = 8, V_ = 64, T_ = 256, T1_ = 257, D_ = 256, H_ = 8, DH_ = 32;
constexpr float EPS = 1e-5f;
constexpr int LDA = 264;                       // padded bf16 row stride
// k_main dynamic smem layout
constexpr int SMA = 64 * LDA * 2;              // 33792  (xn / vf / mixed)
constexpr int SMW = 128 * LDA * 2;             // 67584  (weight half)
constexpr int SMC = 64 * 256 * 4;              // 65536  (f32 accum staging)
constexpr int SM_MAIN = SMA + SMW + SMC;       // 166912
constexpr int SM_QK = 2 * 64 * LDA * 2;        // 67584
}

// ---------------- scratch (device globals) ----------------------------------
__device__ __nv_bfloat16 g_wb[768 * 256];      // bf16 w_qkv (q:0..255,k:256..511,v:512..767)
__device__ __nv_bfloat16 g_wp[256 * 256];      // bf16 w_proj
__device__ __nv_bfloat16 g_xn0[512 * 256];     // LN(x[:, :, 0])  bf16
__device__ __nv_bfloat16 g_xbar[512 * 256];    // masked-mean of LN(x) bf16
__device__ float g_q[512 * 256];
__device__ float g_k[512 * 256];
__device__ __nv_bfloat16 g_attn[8 * 8 * 64 * 64];
__device__ int g_mask_mode;                    // 0 int8, 1 int32, 2 float32

__device__ __forceinline__ float warp_sum(float v) {
#pragma unroll
    for (int o = 16; o; o >>= 1) v += __shfl_xor_sync(0xffffffffu, v, o);
    return v;
}

__device__ __forceinline__ bool mask_at(const void* m, int mode, long i) {
    if (mode == 0) return ((const unsigned char*)m)[i] != 0;
    if (mode == 1) return ((const int*)m)[i] != 0;
    return ((const float*)m)[i] != 0.0f;
}

// ---------------- K0: detect obs_mask storage layout ------------------------
__global__ void k_detect(const unsigned char* m) {
    __shared__ int bad_i32, bad_f32;
    if (threadIdx.x == 0) { bad_i32 = 0; bad_f32 = 0; }
    __syncthreads();
    const unsigned int* w = (const unsigned int*)m;
    int bi = 0, bf = 0;
    for (int i = threadIdx.x; i < (B_ * V_ * T_) / 4; i += blockDim.x) {
        unsigned int x = w[i];
        if (x > 1u) bi = 1;
        if (x != 0u && x != 0x3F800000u) bf = 1;
    }
    if (bi) atomicOr(&bad_i32, 1);
    if (bf) atomicOr(&bad_f32, 1);
    __syncthreads();
    if (threadIdx.x == 0)
        g_mask_mode = (!bad_i32) ? 1 : ((!bad_f32) ? 2 : 0);
}

// ---------------- K1: convert weights to bf16 --------------------------------
__global__ void k_convert(const float* __restrict__ wqkv, const float* __restrict__ wproj) {
    int i = blockIdx.x * blockDim.x + threadIdx.x;   // 262144 threads
    if (i < 768 * 256) g_wb[i] = __float2bfloat16(wqkv[i]);
    else               g_wp[i - 768 * 256] = __float2bfloat16(wproj[i - 768 * 256]);
}

// ---------------- K2: xbar (masked mean of LN) + xn0 -------------------------
// One block per (b,v). 8 warps; warp w owns rows t = w, w+8, ...
__global__ void k_xbar(const float* __restrict__ x, const void* __restrict__ mask,
                       const float* __restrict__ lnw, const float* __restrict__ lnb) {
    int bv = blockIdx.x;
    int w = threadIdx.x >> 5, lane = threadIdx.x & 31;
    int mode = g_mask_mode;

    float lw[8], lb[8], acc[8];
#pragma unroll
    for (int j = 0; j < 8; j++) {
        lw[j] = lnw[lane + 32 * j];
        lb[j] = lnb[lane + 32 * j];
        acc[j] = 0.0f;
    }
    float cnt = 0.0f;

    for (int t = w; t < T1_; t += 8) {
        const float* row = x + ((size_t)bv * T1_ + t) * D_;
        float r[8];
#pragma unroll
        for (int j = 0; j < 8; j++) r[j] = row[lane + 32 * j];
        float s = 0.0f;
#pragma unroll
        for (int j = 0; j < 8; j++) s += r[j];
        s = warp_sum(s);
        float mu = s * (1.0f / 256.0f);
        float v = 0.0f;
#pragma unroll
        for (int j = 0; j < 8; j++) { float d = r[j] - mu; v += d * d; }
        v = warp_sum(v);
        float rs = rsqrtf(v * (1.0f / 256.0f) + EPS);

        bool m = (t == 0) ? true : mask_at(mask, mode, (long)bv * T_ + (t - 1));
        if (m) {
#pragma unroll
            for (int j = 0; j < 8; j++)
                acc[j] += (r[j] - mu) * rs * lw[j] + lb[j];
            cnt += 1.0f;
        }
        if (t == 0) {   // store LN(x at t=0) for the Q projection
#pragma unroll
            for (int j = 0; j < 8; j++)
                g_xn0[bv * D_ + lane + 32 * j] =
                    __float2bfloat16((r[j] - mu) * rs * lw[j] + lb[j]);
        }
    }

    __shared__ float sAcc[8][256];
    __shared__ float sCnt[8];
#pragma unroll
    for (int j = 0; j < 8; j++) sAcc[w][lane + 32 * j] = acc[j];
    if (lane == 0) sCnt[w] = cnt;
    __syncthreads();

    int d = threadIdx.x;
    float tot = 0.0f, c = 0.0f;
#pragma unroll
    for (int i = 0; i < 8; i++) { tot += sAcc[i][d]; c += sCnt[i]; }
    c = fmaxf(c, 1.0f);
    g_xbar[bv * D_ + d] = __float2bfloat16(tot / c);
}

// ---------------- K3: q = xn0 @ Wq^T, k = xbar @ Wk^T (wmma GEMM) ------------
// 64 blocks: mat (q/k) x 8 row-tiles x 4 col-tiles; 256 threads each.
__global__ void k_qk() {
    extern __shared__ char smem[];
    __nv_bfloat16* sA = (__nv_bfloat16*)smem;            // [64][LDA]
    __nv_bfloat16* sB = sA + 64 * LDA;                   // [64][LDA]

    int bid = blockIdx.x;
    int mat = bid >> 5, tile = bid & 31;
    int tr = tile >> 2, tc = tile & 3;
    const __nv_bfloat16* Ag = mat == 0 ? g_xn0 : g_xbar;
    const __nv_bfloat16* Wg = g_wb + (size_t)mat * 256 * 256;
    float* Cg = mat == 0 ? g_q : g_k;

    int tid = threadIdx.x;
    for (int idx = tid; idx < 64 * 32; idx += 256) {
        int r = idx >> 5, c = idx & 31;
        *(uint4*)(sA + r * LDA + c * 8) = *(const uint4*)(Ag + (size_t)(tr * 64 + r) * 256 + c * 8);
        *(uint4*)(sB + r * LDA + c * 8) = *(const uint4*)(Wg + (size_t)(tc * 64 + r) * 256 + c * 8);
    }
    __syncthreads();

    int w = tid >> 5, rt = w & 3, cg = w >> 2;
    wmma::fragment<wmma::accumulator, 16, 16, 16, float> acc[2];
    wmma::fill_fragment(acc[0], 0.0f);
    wmma::fill_fragment(acc[1], 0.0f);
#pragma unroll
    for (int k = 0; k < 16; k++) {
        wmma::fragment<wmma::matrix_a, 16, 16, 16, __nv_bfloat16, wmma::row_major> af;
        wmma::load_matrix_sync(af, sA + (rt * 16) * LDA + k * 16, LDA);
#pragma unroll
        for (int j = 0; j < 2; j++) {
            wmma::fragment<wmma::matrix_b, 16, 16, 16, __nv_bfloat16, wmma::col_major> bf;
            wmma::load_matrix_sync(bf, sB + (cg * 32 + j * 16) * LDA + k * 16, LDA);
            wmma::mma_sync(acc[j], af, bf, acc[j]);
        }
    }
#pragma unroll
    for (int j = 0; j < 2; j++)
        wmma::store_matrix_sync(
            Cg + (size_t)(tr * 64 + rt * 16) * 256 + tc * 64 + cg * 32 + j * 16,
            acc[j], 256, wmma::mem_row_major);
}

// ---------------- K4: attention softmax (per b,h: 64x64) --------------------
__global__ void k_attn() {
    int b = blockIdx.x / H_, h = blockIdx.x % H_;
    __shared__ float qh[64][32], kh[64][32], sc[64][64];
    int tid = threadIdx.x;   // 128 threads

    for (int i = tid; i < 64 * 32; i += 128) {
        int vq = i >> 5, d = i & 31;
        qh[vq][d] = g_q[(size_t)(b * 64 + vq) * D_ + h * 32 + d];
        kh[vq][d] = g_k[(size_t)(b * 64 + vq) * D_ + h * 32 + d];
    }
    __syncthreads();

    const float scale = rsqrtf((float)DH_);
    for (int i = tid; i < 64 * 64; i += 128) {
        int vq = i >> 6, vk = i & 63;
        float s = 0.0f;
#pragma unroll
        for (int d = 0; d < 32; d++) s += qh[vq][d] * kh[vk][d];
        sc[vq][vk] = s * scale;
    }
    __syncthreads();

    if (tid < 64) {
        int vq = tid;
        float mx = -1e30f;
        for (int vk = 0; vk < 64; vk++) mx = fmaxf(mx, sc[vq][vk]);
        float sum = 0.0f;
        for (int vk = 0; vk < 64; vk++) { float e = expf(sc[vq][vk] - mx); sc[vq][vk] = e; sum += e; }
        float inv = 1.0f / sum;
        __nv_bfloat16* dst = g_attn + (size_t)((b * H_ + h) * 64 + vq) * 64;
        for (int vk = 0; vk < 64; vk++) dst[vk] = __float2bfloat16(sc[vq][vk] * inv);
    }
}

// ---------------- K5 helper: C(64x256) = A(64x256) @ W^T, W in 2 halves ------
__device__ __forceinline__ void gemm_full(const __nv_bfloat16* __restrict__ Wg,
                                          const __nv_bfloat16* sA,
                                          __nv_bfloat16* sW, float* sC, int tid) {
    int w = tid >> 5, rt = w & 3, cg = w >> 2;   // 16 warps: 4 row-tiles x 4 col-groups
#pragma unroll
    for (int nh = 0; nh < 2; nh++) {
        for (int idx = tid; idx < 128 * 32; idx += 512) {
            int r = idx >> 5, c = idx & 31;
            *(uint4*)(sW + r * LDA + c * 8) =
                *(const uint4*)(Wg + (size_t)(nh * 128 + r) * 256 + c * 8);
        }
        __syncthreads();

        wmma::fragment<wmma::accumulator, 16, 16, 16, float> acc[2];
        wmma::fill_fragment(acc[0], 0.0f);
        wmma::fill_fragment(acc[1], 0.0f);
#pragma unroll
        for (int k = 0; k < 16; k++) {
            wmma::fragment<wmma::matrix_a, 16, 16, 16, __nv_bfloat16, wmma::row_major> af;
            wmma::load_matrix_sync(af, sA + (rt * 16) * LDA + k * 16, LDA);
#pragma unroll
            for (int j = 0; j < 2; j++) {
                wmma::fragment<wmma::matrix_b, 16, 16, 16, __nv_bfloat16, wmma::col_major> bf;
                wmma::load_matrix_sync(bf, sW + (cg * 32 + j * 16) * LDA + k * 16, LDA);
                wmma::mma_sync(acc[j], af, bf, acc[j]);
            }
        }
#pragma unroll
        for (int j = 0; j < 2; j++)
            wmma::store_matrix_sync(sC + (rt * 16) * 256 + nh * 128 + cg * 32 + j * 16,
                                    acc[j], 256, wmma::mem_row_major);
        __syncthreads();
    }
}

// ---------------- K5: fused LN + V-GEMM + attn-mix + proj + residual ---------
// One block per (b, t): 64 rows x 256 cols. 512 threads.
__global__ void __launch_bounds__(512, 1)
k_main(const float* __restrict__ x, const float* __restrict__ lnw,
       const float* __restrict__ lnb, const float* __restrict__ bproj,
       float* __restrict__ out) {
    extern __shared__ char smem[];
    __nv_bfloat16* sA = (__nv_bfloat16*)smem;             // [64][LDA]
    __nv_bfloat16* sW = (__nv_bfloat16*)(smem + SMA);     // [128][LDA]
    float*         sC = (float*)(smem + SMA + SMW);       // [64][256]

    int b = blockIdx.x / T1_, t = blockIdx.x % T1_;
    int tid = threadIdx.x, w = tid >> 5, lane = tid & 31;
    int rt = w & 3, cg = w >> 2;

    // ---- LayerNorm of (b, :, t, :) tile -> sA (bf16) ----
    for (int v = w; v < 64; v += 16) {
        const float* row = x + ((size_t)(b * 64 + v) * T1_ + t) * D_;
        float r[8];
#pragma unroll
        for (int j = 0; j < 8; j++) r[j] = row[lane + 32 * j];
        float s = 0.0f;
#pragma unroll
        for (int j = 0; j < 8; j++) s += r[j];
        s = warp_sum(s);
        float mu = s * (1.0f / 256.0f);
        float var = 0.0f;
#pragma unroll
        for (int j = 0; j < 8; j++) { float d = r[j] - mu; var += d * d; }
        var = warp_sum(var);
        float rs = rsqrtf(var * (1.0f / 256.0f) + EPS);
#pragma unroll
        for (int j = 0; j < 8; j++) {
            int d = lane + 32 * j;
            sA[v * LDA + d] = __float2bfloat16((r[j] - mu) * rs * lnw[d] + lnb[d]);
        }
    }
    __syncthreads();

    // ---- vf = xn @ Wv^T ----
    gemm_full(g_wb + (size_t)512 * 256, sA, sW, sC, tid);

    // sA (xn) no longer needed: convert vf -> sA (bf16)
    for (int i = tid; i < 64 * 256; i += 512) {
        int v = i >> 8, d = i & 255;
        sA[v * LDA + d] = __float2bfloat16(sC[i]);
    }
    __syncthreads();

    // ---- attn mixing: per head h, attn_h(64x64) @ vf_h(64x32) ----
#pragma unroll
    for (int hh = 0; hh < 2; hh++) {
        int h = cg * 2 + hh;
        wmma::fragment<wmma::accumulator, 16, 16, 16, float> ac2[2];
        wmma::fill_fragment(ac2[0], 0.0f);
        wmma::fill_fragment(ac2[1], 0.0f);
#pragma unroll
        for (int kt = 0; kt < 4; kt++) {
            wmma::fragment<wmma::matrix_a, 16, 16, 16, __nv_bfloat16, wmma::row_major> af;
            wmma::load_matrix_sync(af,
                g_attn + (size_t)((b * H_ + h) * 64 + rt * 16) * 64 + kt * 16, 64);
#pragma unroll
            for (int j2 = 0; j2 < 2; j2++) {
                wmma::fragment<wmma::matrix_b, 16, 16, 16, __nv_bfloat16, wmma::row_major> bf;
                wmma::load_matrix_sync(bf, sA + (kt * 16) * LDA + h * 32 + j2 * 16, LDA);
                wmma::mma_sync(ac2[j2], af, bf, ac2[j2]);
            }
        }
#pragma unroll
        for (int j2 = 0; j2 < 2; j2++)
            wmma::store_matrix_sync(sC + (rt * 16) * 256 + h * 32 + j2 * 16, ac2[j2],
                                    256, wmma::mem_row_major);
    }
    __syncthreads();

    // mixed -> sA (bf16)
    for (int i = tid; i < 64 * 256; i += 512) {
        int v = i >> 8, d = i & 255;
        sA[v * LDA + d] = __float2bfloat16(sC[i]);
    }
    __syncthreads();

    // ---- proj = mixed @ Wproj^T ----
    gemm_full(g_wp, sA, sW, sC, tid);

    // ---- epilogue: out = x + proj + b_proj ----
    for (int i = tid; i < 64 * 256; i += 512) {
        int v = i >> 8, d = i & 255;
        size_t gi = ((size_t)(b * 64 + v) * T1_ + t) * D_ + d;
        out[gi] = sC[i] + bproj[d] + x[gi];
    }
}

// ---------------- launch ----------------------------------------------------
extern "C" void kernel_launch(void* const* d_in, const int* in_sizes, int n_in,
                              void* d_out, int out_size) {
    const float* x     = (const float*)d_in[0];
    const void*  mask  = d_in[1];
    const float* lnw   = (const float*)d_in[2];
    const float* lnb   = (const float*)d_in[3];
    const float* wqkv  = (const float*)d_in[4];
    const float* wproj = (const float*)d_in[5];
    const float* bproj = (const float*)d_in[6];
    float* out = (float*)d_out;

    cudaFuncSetAttribute(k_main, cudaFuncAttributeMaxDynamicSharedMemorySize, SM_MAIN);
    cudaFuncSetAttribute(k_qk, cudaFuncAttributeMaxDynamicSharedMemorySize, SM_QK);

    k_detect<<<1, 256>>>((const unsigned char*)mask);
    k_convert<<<1024, 256>>>(wqkv, wproj);
    k_xbar<<<B_ * V_, 256>>>(x, mask, lnw, lnb);
    k_qk<<<64, 256, SM_QK>>>();
    k_attn<<<B_ * H_, 128>>>();
    k_main<<<B_ * T1_, 512, SM_MAIN>>>(x, lnw, lnb, bproj, out);
}

// round 3
// speedup vs baseline: 2.9334x; 1.3296x over previous
#include <cuda_runtime.h>
#include <cuda_bf16.h>
#include <mma.h>

using namespace nvcuda;

namespace {
constexpr int B_ = 8, V_ = 64, T_ = 256, T1_ = 257, D_ = 256, H_ = 8, DH_ = 32;
constexpr float EPS = 1e-5f;
constexpr int LDA = 264;                 // bf16 elems per sA row (528B stride)
constexpr int LDW = 72;                  // bf16 elems per weight-chunk row (144B)
constexpr int LDC = 264;                 // f32 elems per sC row
// k_main dynamic smem layout (bytes)
constexpr int OFF_A  = 0;                           // [128][LDA] bf16 = 67584
constexpr int OFF_W0 = 128 * LDA * 2;               // [256][LDW] bf16 = 36864
constexpr int OFF_W1 = OFF_W0 + 256 * LDW * 2;
constexpr int OFF_C  = OFF_W1 + 256 * LDW * 2;      // [64][LDC] f32 = 67584
constexpr int SM_MAIN = OFF_C + 64 * LDC * 4;       // 208896
constexpr int SM_QK = 2 * 64 * LDA * 2;             // 67584
}

// ---------------- scratch (device globals) ----------------------------------
__device__ __nv_bfloat16 g_wb[768 * 256];      // bf16 w_qkv
__device__ __nv_bfloat16 g_wp[256 * 256];      // bf16 w_proj
__device__ __nv_bfloat16 g_xn0[512 * 256];     // LN(x[:,:,0]) bf16
__device__ __nv_bfloat16 g_xbar[512 * 256];    // masked-mean of LN(x) bf16
__device__ float g_q[512 * 256];
__device__ float g_k[512 * 256];
__device__ __nv_bfloat16 g_attn[8 * 8 * 64 * 64];
__device__ int g_mask_mode;

__device__ __forceinline__ float warp_sum(float v) {
#pragma unroll
    for (int o = 16; o; o >>= 1) v += __shfl_xor_sync(0xffffffffu, v, o);
    return v;
}

__device__ __forceinline__ bool mask_at(const void* m, int mode, long i) {
    if (mode == 0) return ((const unsigned char*)m)[i] != 0;
    if (mode == 1) return ((const int*)m)[i] != 0;
    return ((const float*)m)[i] != 0.0f;
}

__device__ __forceinline__ void cp16(void* s, const void* g) {
    unsigned sa = (unsigned)__cvta_generic_to_shared(s);
    asm volatile("cp.async.cg.shared.global [%0], [%1], 16;\n" :: "r"(sa), "l"(g));
}
__device__ __forceinline__ void cp_commit() {
    asm volatile("cp.async.commit_group;\n");
}
template <int N>
__device__ __forceinline__ void cp_wait() {
    asm volatile("cp.async.wait_group %0;\n" :: "n"(N));
}

// ---------------- K0: detect obs_mask storage layout ------------------------
__global__ void k_detect(const unsigned char* m) {
    __shared__ int bad_i32, bad_f32;
    if (threadIdx.x == 0) { bad_i32 = 0; bad_f32 = 0; }
    __syncthreads();
    const unsigned int* w = (const unsigned int*)m;
    int bi = 0, bf = 0;
    for (int i = threadIdx.x; i < (B_ * V_ * T_) / 4; i += blockDim.x) {
        unsigned int x = w[i];
        if (x > 1u) bi = 1;
        if (x != 0u && x != 0x3F800000u) bf = 1;
    }
    if (bi) atomicOr(&bad_i32, 1);
    if (bf) atomicOr(&bad_f32, 1);
    __syncthreads();
    if (threadIdx.x == 0)
        g_mask_mode = (!bad_i32) ? 1 : ((!bad_f32) ? 2 : 0);
}

// ---------------- K1: convert weights to bf16 --------------------------------
__global__ void k_convert(const float* __restrict__ wqkv, const float* __restrict__ wproj) {
    int i = blockIdx.x * blockDim.x + threadIdx.x;
    if (i < 768 * 256) g_wb[i] = __float2bfloat16(wqkv[i]);
    else               g_wp[i - 768 * 256] = __float2bfloat16(wproj[i - 768 * 256]);
}

// ---------------- K2: xbar (masked mean of LN) + xn0 -------------------------
__global__ void k_xbar(const float* __restrict__ x, const void* __restrict__ mask,
                       const float* __restrict__ lnw, const float* __restrict__ lnb) {
    int bv = blockIdx.x;
    int w = threadIdx.x >> 5, lane = threadIdx.x & 31;
    int mode = g_mask_mode;

    float lw[8], lb[8], acc[8];
#pragma unroll
    for (int j = 0; j < 8; j++) {
        lw[j] = lnw[lane + 32 * j];
        lb[j] = lnb[lane + 32 * j];
        acc[j] = 0.0f;
    }
    float cnt = 0.0f;

    for (int t = w; t < T1_; t += 8) {
        const float* row = x + ((size_t)bv * T1_ + t) * D_;
        float r[8];
#pragma unroll
        for (int j = 0; j < 8; j++) r[j] = row[lane + 32 * j];
        float s = 0.0f;
#pragma unroll
        for (int j = 0; j < 8; j++) s += r[j];
        s = warp_sum(s);
        float mu = s * (1.0f / 256.0f);
        float v = 0.0f;
#pragma unroll
        for (int j = 0; j < 8; j++) { float d = r[j] - mu; v += d * d; }
        v = warp_sum(v);
        float rs = rsqrtf(v * (1.0f / 256.0f) + EPS);

        bool m = (t == 0) ? true : mask_at(mask, mode, (long)bv * T_ + (t - 1));
        if (m) {
#pragma unroll
            for (int j = 0; j < 8; j++)
                acc[j] += (r[j] - mu) * rs * lw[j] + lb[j];
            cnt += 1.0f;
        }
        if (t == 0) {
#pragma unroll
            for (int j = 0; j < 8; j++)
                g_xn0[bv * D_ + lane + 32 * j] =
                    __float2bfloat16((r[j] - mu) * rs * lw[j] + lb[j]);
        }
    }

    __shared__ float sAcc[8][256];
    __shared__ float sCnt[8];
#pragma unroll
    for (int j = 0; j < 8; j++) sAcc[w][lane + 32 * j] = acc[j];
    if (lane == 0) sCnt[w] = cnt;
    __syncthreads();

    int d = threadIdx.x;
    float tot = 0.0f, c = 0.0f;
#pragma unroll
    for (int i = 0; i < 8; i++) { tot += sAcc[i][d]; c += sCnt[i]; }
    c = fmaxf(c, 1.0f);
    g_xbar[bv * D_ + d] = __float2bfloat16(tot / c);
}

// ---------------- K3: q = xn0 @ Wq^T, k = xbar @ Wk^T ------------------------
__global__ void k_qk() {
    extern __shared__ char smem[];
    __nv_bfloat16* sA = (__nv_bfloat16*)smem;
    __nv_bfloat16* sB = sA + 64 * LDA;

    int bid = blockIdx.x;
    int mat = bid >> 5, tile = bid & 31;
    int tr = tile >> 2, tc = tile & 3;
    const __nv_bfloat16* Ag = mat == 0 ? g_xn0 : g_xbar;
    const __nv_bfloat16* Wg = g_wb + (size_t)mat * 256 * 256;
    float* Cg = mat == 0 ? g_q : g_k;

    int tid = threadIdx.x;
    for (int idx = tid; idx < 64 * 32; idx += 256) {
        int r = idx >> 5, c = idx & 31;
        *(uint4*)(sA + r * LDA + c * 8) = *(const uint4*)(Ag + (size_t)(tr * 64 + r) * 256 + c * 8);
        *(uint4*)(sB + r * LDA + c * 8) = *(const uint4*)(Wg + (size_t)(tc * 64 + r) * 256 + c * 8);
    }
    __syncthreads();

    int w = tid >> 5, rt = w & 3, cg = w >> 2;
    wmma::fragment<wmma::accumulator, 16, 16, 16, float> acc[2];
    wmma::fill_fragment(acc[0], 0.0f);
    wmma::fill_fragment(acc[1], 0.0f);
#pragma unroll
    for (int k = 0; k < 16; k++) {
        wmma::fragment<wmma::matrix_a, 16, 16, 16, __nv_bfloat16, wmma::row_major> af;
        wmma::load_matrix_sync(af, sA + (rt * 16) * LDA + k * 16, LDA);
#pragma unroll
        for (int j = 0; j < 2; j++) {
            wmma::fragment<wmma::matrix_b, 16, 16, 16, __nv_bfloat16, wmma::col_major> bf;
            wmma::load_matrix_sync(bf, sB + (cg * 32 + j * 16) * LDA + k * 16, LDA);
            wmma::mma_sync(acc[j], af, bf, acc[j]);
        }
    }
#pragma unroll
    for (int j = 0; j < 2; j++)
        wmma::store_matrix_sync(
            Cg + (size_t)(tr * 64 + rt * 16) * 256 + tc * 64 + cg * 32 + j * 16,
            acc[j], 256, wmma::mem_row_major);
}

// ---------------- K4: attention softmax (per b,h: 64x64) --------------------
__global__ void k_attn() {
    int b = blockIdx.x / H_, h = blockIdx.x % H_;
    __shared__ float qh[64][32], kh[64][32], sc[64][64];
    int tid = threadIdx.x;

    for (int i = tid; i < 64 * 32; i += 128) {
        int vq = i >> 5, d = i & 31;
        qh[vq][d] = g_q[(size_t)(b * 64 + vq) * D_ + h * 32 + d];
        kh[vq][d] = g_k[(size_t)(b * 64 + vq) * D_ + h * 32 + d];
    }
    __syncthreads();

    const float scale = rsqrtf((float)DH_);
    for (int i = tid; i < 64 * 64; i += 128) {
        int vq = i >> 6, vk = i & 63;
        float s = 0.0f;
#pragma unroll
        for (int d = 0; d < 32; d++) s += qh[vq][d] * kh[vk][d];
        sc[vq][vk] = s * scale;
    }
    __syncthreads();

    if (tid < 64) {
        int vq = tid;
        float mx = -1e30f;
        for (int vk = 0; vk < 64; vk++) mx = fmaxf(mx, sc[vq][vk]);
        float sum = 0.0f;
        for (int vk = 0; vk < 64; vk++) { float e = expf(sc[vq][vk] - mx); sc[vq][vk] = e; sum += e; }
        float inv = 1.0f / sum;
        __nv_bfloat16* dst = g_attn + (size_t)((b * H_ + h) * 64 + vq) * 64;
        for (int vk = 0; vk < 64; vk++) dst[vk] = __float2bfloat16(sc[vq][vk] * inv);
    }
}

// ---------------- k_main helpers ---------------------------------------------
// load one K-chunk of weights: W[n=0..255][kc*64 .. kc*64+63] -> sW [256][LDW]
__device__ __forceinline__ void load_wchunk(__nv_bfloat16* sW,
                                            const __nv_bfloat16* __restrict__ Wg,
                                            int kc, int tid) {
#pragma unroll
    for (int i = 0; i < 4; i++) {
        int idx = tid + i * 512;            // 0..2047
        int n = idx >> 3, seg = idx & 7;
        cp16(sW + n * LDW + seg * 8, Wg + (size_t)n * 256 + kc * 64 + seg * 8);
    }
    cp_commit();
}

using FragAcc = wmma::fragment<wmma::accumulator, 16, 16, 16, float>;
using FragA = wmma::fragment<wmma::matrix_a, 16, 16, 16, __nv_bfloat16, wmma::row_major>;
using FragBc = wmma::fragment<wmma::matrix_b, 16, 16, 16, __nv_bfloat16, wmma::col_major>;
using FragBr = wmma::fragment<wmma::matrix_b, 16, 16, 16, __nv_bfloat16, wmma::row_major>;

// C(128x256) += A(128x256,bf16 in sA) @ W(256x256)^T, double-buffered chunks.
// Warp w: rows rb*32..+32, cols cb*64..+64. acc[2][4] left in registers.
__device__ __forceinline__ void gemm_k256(const __nv_bfloat16* __restrict__ Wg,
                                          const __nv_bfloat16* sA,
                                          __nv_bfloat16* sW0, __nv_bfloat16* sW1,
                                          FragAcc acc[2][4], int tid) {
    int w = tid >> 5, rb = w >> 2, cb = w & 3;
#pragma unroll
    for (int i = 0; i < 2; i++)
#pragma unroll
        for (int j = 0; j < 4; j++) wmma::fill_fragment(acc[i][j], 0.0f);

    load_wchunk(sW0, Wg, 0, tid);
#pragma unroll
    for (int kc = 0; kc < 4; kc++) {
        __nv_bfloat16* cur = (kc & 1) ? sW1 : sW0;
        __nv_bfloat16* nxt = (kc & 1) ? sW0 : sW1;
        if (kc < 3) {
            load_wchunk(nxt, Wg, kc + 1, tid);
            cp_wait<1>();
        } else {
            cp_wait<0>();
        }
        __syncthreads();
#pragma unroll
        for (int s = 0; s < 4; s++) {
            int kk = s * 16;
            FragA a0, a1;
            wmma::load_matrix_sync(a0, sA + (rb * 32) * LDA + kc * 64 + kk, LDA);
            wmma::load_matrix_sync(a1, sA + (rb * 32 + 16) * LDA + kc * 64 + kk, LDA);
#pragma unroll
            for (int j = 0; j < 4; j++) {
                FragBc bf;
                wmma::load_matrix_sync(bf, cur + (cb * 64 + j * 16) * LDW + kk, LDW);
                wmma::mma_sync(acc[0][j], a0, bf, acc[0][j]);
                wmma::mma_sync(acc[1][j], a1, bf, acc[1][j]);
            }
        }
        __syncthreads();   // cur fully consumed before it is refilled
    }
}

// stage one 64-row half of C (f32 frags) into sC (warps with rb>>1==h store)
__device__ __forceinline__ void stage_half(FragAcc acc[2][4], float* sC, int tid, int h) {
    int w = tid >> 5, rb = w >> 2, cb = w & 3;
    if ((rb >> 1) == h) {
#pragma unroll
        for (int i = 0; i < 2; i++)
#pragma unroll
            for (int j = 0; j < 4; j++)
                wmma::store_matrix_sync(sC + ((rb & 1) * 32 + i * 16) * LDC + cb * 64 + j * 16,
                                        acc[i][j], LDC, wmma::mem_row_major);
    }
}

// ---------------- K5: fused LN + V-GEMM + attn-mix + proj + residual ---------
// One block per (b, t-pair): 128 rows (2 t) x 256 cols. 512 threads.
__global__ void __launch_bounds__(512, 1)
k_main(const float* __restrict__ x, const float* __restrict__ lnw,
       const float* __restrict__ lnb, const float* __restrict__ bproj,
       float* __restrict__ out) {
    extern __shared__ char smem[];
    __nv_bfloat16* sA  = (__nv_bfloat16*)(smem + OFF_A);
    __nv_bfloat16* sW0 = (__nv_bfloat16*)(smem + OFF_W0);
    __nv_bfloat16* sW1 = (__nv_bfloat16*)(smem + OFF_W1);
    float*         sC  = (float*)(smem + OFF_C);

    int b = blockIdx.x / 129, tp = blockIdx.x % 129;
    int t0 = tp * 2, t1 = min(t0 + 1, 256);
    int tid = threadIdx.x, w = tid >> 5, lane = tid & 31;

    // ---- LayerNorm: 128 rows (r<64 -> t0, else t1) -> sA bf16 ----
    for (int r = w; r < 128; r += 16) {
        int t = (r < 64) ? t0 : t1;
        int v = r & 63;
        const float* row = x + ((size_t)(b * 64 + v) * T1_ + t) * D_;
        float rr[8];
#pragma unroll
        for (int j = 0; j < 8; j++) rr[j] = row[lane + 32 * j];
        float s = 0.0f;
#pragma unroll
        for (int j = 0; j < 8; j++) s += rr[j];
        s = warp_sum(s);
        float mu = s * (1.0f / 256.0f);
        float var = 0.0f;
#pragma unroll
        for (int j = 0; j < 8; j++) { float d = rr[j] - mu; var += d * d; }
        var = warp_sum(var);
        float rs = rsqrtf(var * (1.0f / 256.0f) + EPS);
#pragma unroll
        for (int j = 0; j < 8; j++) {
            int d = lane + 32 * j;
            sA[r * LDA + d] = __float2bfloat16((rr[j] - mu) * rs * lnw[d] + lnb[d]);
        }
    }
    __syncthreads();

    // ---- vf = xn @ Wv^T ----
    {
        FragAcc acc[2][4];
        gemm_k256(g_wb + (size_t)512 * 256, sA, sW0, sW1, acc, tid);
#pragma unroll
        for (int h = 0; h < 2; h++) {
            stage_half(acc, sC, tid, h);
            __syncthreads();
            for (int i = tid; i < 64 * 256; i += 512) {
                int r = i >> 8, d = i & 255;
                sA[(h * 64 + r) * LDA + d] = __float2bfloat16(sC[r * LDC + d]);
            }
            __syncthreads();
        }
    }

    // ---- attn mixing: warp w -> tsub = w>>3, head = w&7 ----
    {
        int tsub = w >> 3, h = w & 7;
        FragAcc ac2[4][2];
#pragma unroll
        for (int i = 0; i < 4; i++) {
            wmma::fill_fragment(ac2[i][0], 0.0f);
            wmma::fill_fragment(ac2[i][1], 0.0f);
        }
        const __nv_bfloat16* attn = g_attn + (size_t)(b * H_ + h) * 64 * 64;
#pragma unroll
        for (int kt = 0; kt < 4; kt++) {
            FragBr bf0, bf1;
            wmma::load_matrix_sync(bf0, sA + (tsub * 64 + kt * 16) * LDA + h * 32, LDA);
            wmma::load_matrix_sync(bf1, sA + (tsub * 64 + kt * 16) * LDA + h * 32 + 16, LDA);
#pragma unroll
            for (int rt = 0; rt < 4; rt++) {
                FragA af;
                wmma::load_matrix_sync(af, attn + (rt * 16) * 64 + kt * 16, 64);
                wmma::mma_sync(ac2[rt][0], af, bf0, ac2[rt][0]);
                wmma::mma_sync(ac2[rt][1], af, bf1, ac2[rt][1]);
            }
        }
        __syncthreads();
#pragma unroll
        for (int ts = 0; ts < 2; ts++) {
            if (tsub == ts) {
#pragma unroll
                for (int rt = 0; rt < 4; rt++) {
                    wmma::store_matrix_sync(sC + (rt * 16) * LDC + h * 32, ac2[rt][0],
                                            LDC, wmma::mem_row_major);
                    wmma::store_matrix_sync(sC + (rt * 16) * LDC + h * 32 + 16, ac2[rt][1],
                                            LDC, wmma::mem_row_major);
                }
            }
            __syncthreads();
            for (int i = tid; i < 64 * 256; i += 512) {
                int r = i >> 8, d = i & 255;
                sA[(ts * 64 + r) * LDA + d] = __float2bfloat16(sC[r * LDC + d]);
            }
            __syncthreads();
        }
    }

    // ---- proj = mixed @ Wp^T, + residual epilogue ----
    {
        FragAcc acc[2][4];
        gemm_k256(g_wp, sA, sW0, sW1, acc, tid);
#pragma unroll
        for (int h = 0; h < 2; h++) {
            stage_half(acc, sC, tid, h);
            __syncthreads();
            int t = (h == 0) ? t0 : t1;
            if (h == 0 || t1 != t0) {
                for (int i = tid; i < 64 * 256; i += 512) {
                    int r = i >> 8, d = i & 255;
                    size_t gi = ((size_t)(b * 64 + r) * T1_ + t) * D_ + d;
                    out[gi] = sC[r * LDC + d] + bproj[d] + x[gi];
                }
            }
            __syncthreads();
        }
    }
}

// ---------------- launch ----------------------------------------------------
extern "C" void kernel_launch(void* const* d_in, const int* in_sizes, int n_in,
                              void* d_out, int out_size) {
    const float* x     = (const float*)d_in[0];
    const void*  mask  = d_in[1];
    const float* lnw   = (const float*)d_in[2];
    const float* lnb   = (const float*)d_in[3];
    const float* wqkv  = (const float*)d_in[4];
    const float* wproj = (const float*)d_in[5];
    const float* bproj = (const float*)d_in[6];
    float* out = (float*)d_out;

    cudaFuncSetAttribute(k_main, cudaFuncAttributeMaxDynamicSharedMemorySize, SM_MAIN);
    cudaFuncSetAttribute(k_qk, cudaFuncAttributeMaxDynamicSharedMemorySize, SM_QK);

    k_detect<<<1, 256>>>((const unsigned char*)mask);
    k_convert<<<1024, 256>>>(wqkv, wproj);
    k_xbar<<<B_ * V_, 256>>>(x, mask, lnw, lnb);
    k_qk<<<64, 256, SM_QK>>>();
    k_attn<<<B_ * H_, 128>>>();
    k_main<<<B_ * 129, 512, SM_MAIN>>>(x, lnw, lnb, bproj, out);
}

// round 4
// speedup vs baseline: 3.6678x; 1.2504x over previous
#include <cuda_runtime.h>
#include <cuda_bf16.h>
#include <mma.h>

using namespace nvcuda;

namespace {
constexpr int B_ = 8, V_ = 64, T_ = 256, T1_ = 257, D_ = 256, H_ = 8, DH_ = 32;
constexpr float EPS = 1e-5f;
constexpr int LDA = 264;                 // bf16 elems per sA row (528B)
constexpr int LDW = 72;                  // bf16 elems per weight-chunk row (144B)
constexpr int LDT = 72;                  // bf16 elems per attn row
// k_main dynamic smem layout (bytes)
constexpr int OFF_A  = 0;                            // [128][LDA] bf16 = 67584
constexpr int OFF_W0 = 128 * LDA * 2;                // [256][LDW] = 36864
constexpr int OFF_W1 = OFF_W0 + 256 * LDW * 2;       // 36864
constexpr int OFF_AT = OFF_W1 + 256 * LDW * 2;       // [8*64][LDT] = 73728
constexpr int SM_MAIN = OFF_AT + 8 * 64 * LDT * 2;   // 215040
constexpr int SM_QK = 2 * 64 * LDA * 2;              // 67584
}

// ---------------- scratch (device globals) ----------------------------------
__device__ __nv_bfloat16 g_wb[768 * 256];      // bf16 w_qkv
__device__ __nv_bfloat16 g_wp[256 * 256];      // bf16 w_proj
__device__ __nv_bfloat16 g_xn0[512 * 256];     // LN(x[:,:,0]) bf16
__device__ __nv_bfloat16 g_xbar[512 * 256];    // masked-mean of LN(x) bf16
__device__ float g_q[512 * 256];
__device__ float g_k[512 * 256];
__device__ __nv_bfloat16 g_attn[8 * 8 * 64 * 64];
__device__ int g_mask_mode;

__device__ __forceinline__ float warp_sum(float v) {
#pragma unroll
    for (int o = 16; o; o >>= 1) v += __shfl_xor_sync(0xffffffffu, v, o);
    return v;
}

__device__ __forceinline__ bool mask_at(const void* m, int mode, long i) {
    if (mode == 0) return ((const unsigned char*)m)[i] != 0;
    if (mode == 1) return ((const int*)m)[i] != 0;
    return ((const float*)m)[i] != 0.0f;
}

__device__ __forceinline__ void cp16(void* s, const void* g) {
    unsigned sa = (unsigned)__cvta_generic_to_shared(s);
    asm volatile("cp.async.cg.shared.global [%0], [%1], 16;\n" :: "r"(sa), "l"(g));
}
__device__ __forceinline__ void cp_commit() {
    asm volatile("cp.async.commit_group;\n");
}
template <int N>
__device__ __forceinline__ void cp_wait() {
    asm volatile("cp.async.wait_group %0;\n" :: "n"(N));
}

// ---------------- raw tensor-core primitives ---------------------------------
__device__ __forceinline__ void ldsm_x4(unsigned r[4], const __nv_bfloat16* p) {
    unsigned a = (unsigned)__cvta_generic_to_shared(p);
    asm volatile("ldmatrix.sync.aligned.m8n8.x4.shared.b16 {%0,%1,%2,%3}, [%4];"
                 : "=r"(r[0]), "=r"(r[1]), "=r"(r[2]), "=r"(r[3]) : "r"(a));
}
__device__ __forceinline__ void ldsm_x4t(unsigned r[4], const __nv_bfloat16* p) {
    unsigned a = (unsigned)__cvta_generic_to_shared(p);
    asm volatile("ldmatrix.sync.aligned.m8n8.x4.trans.shared.b16 {%0,%1,%2,%3}, [%4];"
                 : "=r"(r[0]), "=r"(r[1]), "=r"(r[2]), "=r"(r[3]) : "r"(a));
}
__device__ __forceinline__ void mma_bf16(float c[4], const unsigned a[4], const unsigned* b) {
    asm volatile(
        "mma.sync.aligned.m16n8k16.row.col.f32.bf16.bf16.f32 "
        "{%0,%1,%2,%3},{%4,%5,%6,%7},{%8,%9},{%0,%1,%2,%3};"
        : "+f"(c[0]), "+f"(c[1]), "+f"(c[2]), "+f"(c[3])
        : "r"(a[0]), "r"(a[1]), "r"(a[2]), "r"(a[3]), "r"(b[0]), "r"(b[1]));
}

// ---------------- K0: detect obs_mask storage layout ------------------------
__global__ void k_detect(const unsigned char* m) {
    __shared__ int bad_i32, bad_f32;
    if (threadIdx.x == 0) { bad_i32 = 0; bad_f32 = 0; }
    __syncthreads();
    const unsigned int* w = (const unsigned int*)m;
    int bi = 0, bf = 0;
    for (int i = threadIdx.x; i < (B_ * V_ * T_) / 4; i += blockDim.x) {
        unsigned int x = w[i];
        if (x > 1u) bi = 1;
        if (x != 0u && x != 0x3F800000u) bf = 1;
    }
    if (bi) atomicOr(&bad_i32, 1);
    if (bf) atomicOr(&bad_f32, 1);
    __syncthreads();
    if (threadIdx.x == 0)
        g_mask_mode = (!bad_i32) ? 1 : ((!bad_f32) ? 2 : 0);
}

// ---------------- K1: convert weights to bf16 --------------------------------
__global__ void k_convert(const float* __restrict__ wqkv, const float* __restrict__ wproj) {
    int i = blockIdx.x * blockDim.x + threadIdx.x;
    if (i < 768 * 256) g_wb[i] = __float2bfloat16(wqkv[i]);
    else               g_wp[i - 768 * 256] = __float2bfloat16(wproj[i - 768 * 256]);
}

// ---------------- K2: xbar (masked mean of LN) + xn0 -------------------------
__global__ void k_xbar(const float* __restrict__ x, const void* __restrict__ mask,
                       const float* __restrict__ lnw, const float* __restrict__ lnb) {
    int bv = blockIdx.x;
    int w = threadIdx.x >> 5, lane = threadIdx.x & 31;
    int mode = g_mask_mode;

    float lw[8], lb[8], acc[8];
#pragma unroll
    for (int j = 0; j < 8; j++) {
        lw[j] = lnw[lane + 32 * j];
        lb[j] = lnb[lane + 32 * j];
        acc[j] = 0.0f;
    }
    float cnt = 0.0f;

    for (int t = w; t < T1_; t += 8) {
        const float* row = x + ((size_t)bv * T1_ + t) * D_;
        float r[8];
#pragma unroll
        for (int j = 0; j < 8; j++) r[j] = row[lane + 32 * j];
        float s = 0.0f;
#pragma unroll
        for (int j = 0; j < 8; j++) s += r[j];
        s = warp_sum(s);
        float mu = s * (1.0f / 256.0f);
        float v = 0.0f;
#pragma unroll
        for (int j = 0; j < 8; j++) { float d = r[j] - mu; v += d * d; }
        v = warp_sum(v);
        float rs = rsqrtf(v * (1.0f / 256.0f) + EPS);

        bool m = (t == 0) ? true : mask_at(mask, mode, (long)bv * T_ + (t - 1));
        if (m) {
#pragma unroll
            for (int j = 0; j < 8; j++)
                acc[j] += (r[j] - mu) * rs * lw[j] + lb[j];
            cnt += 1.0f;
        }
        if (t == 0) {
#pragma unroll
            for (int j = 0; j < 8; j++)
                g_xn0[bv * D_ + lane + 32 * j] =
                    __float2bfloat16((r[j] - mu) * rs * lw[j] + lb[j]);
        }
    }

    __shared__ float sAcc[8][256];
    __shared__ float sCnt[8];
#pragma unroll
    for (int j = 0; j < 8; j++) sAcc[w][lane + 32 * j] = acc[j];
    if (lane == 0) sCnt[w] = cnt;
    __syncthreads();

    int d = threadIdx.x;
    float tot = 0.0f, c = 0.0f;
#pragma unroll
    for (int i = 0; i < 8; i++) { tot += sAcc[i][d]; c += sCnt[i]; }
    c = fmaxf(c, 1.0f);
    g_xbar[bv * D_ + d] = __float2bfloat16(tot / c);
}

// ---------------- K3: q = xn0 @ Wq^T, k = xbar @ Wk^T ------------------------
__global__ void k_qk() {
    extern __shared__ char smem[];
    __nv_bfloat16* sA = (__nv_bfloat16*)smem;
    __nv_bfloat16* sB = sA + 64 * LDA;

    int bid = blockIdx.x;
    int mat = bid >> 5, tile = bid & 31;
    int tr = tile >> 2, tc = tile & 3;
    const __nv_bfloat16* Ag = mat == 0 ? g_xn0 : g_xbar;
    const __nv_bfloat16* Wg = g_wb + (size_t)mat * 256 * 256;
    float* Cg = mat == 0 ? g_q : g_k;

    int tid = threadIdx.x;
    for (int idx = tid; idx < 64 * 32; idx += 256) {
        int r = idx >> 5, c = idx & 31;
        *(uint4*)(sA + r * LDA + c * 8) = *(const uint4*)(Ag + (size_t)(tr * 64 + r) * 256 + c * 8);
        *(uint4*)(sB + r * LDA + c * 8) = *(const uint4*)(Wg + (size_t)(tc * 64 + r) * 256 + c * 8);
    }
    __syncthreads();

    int w = tid >> 5, rt = w & 3, cg = w >> 2;
    wmma::fragment<wmma::accumulator, 16, 16, 16, float> acc[2];
    wmma::fill_fragment(acc[0], 0.0f);
    wmma::fill_fragment(acc[1], 0.0f);
#pragma unroll
    for (int k = 0; k < 16; k++) {
        wmma::fragment<wmma::matrix_a, 16, 16, 16, __nv_bfloat16, wmma::row_major> af;
        wmma::load_matrix_sync(af, sA + (rt * 16) * LDA + k * 16, LDA);
#pragma unroll
        for (int j = 0; j < 2; j++) {
            wmma::fragment<wmma::matrix_b, 16, 16, 16, __nv_bfloat16, wmma::col_major> bf;
            wmma::load_matrix_sync(bf, sB + (cg * 32 + j * 16) * LDA + k * 16, LDA);
            wmma::mma_sync(acc[j], af, bf, acc[j]);
        }
    }
#pragma unroll
    for (int j = 0; j < 2; j++)
        wmma::store_matrix_sync(
            Cg + (size_t)(tr * 64 + rt * 16) * 256 + tc * 64 + cg * 32 + j * 16,
            acc[j], 256, wmma::mem_row_major);
}

// ---------------- K4: attention softmax (per b,h: 64x64) --------------------
__global__ void k_attn() {
    int b = blockIdx.x / H_, h = blockIdx.x % H_;
    __shared__ float qh[64][32], kh[64][32], sc[64][64];
    int tid = threadIdx.x;

    for (int i = tid; i < 64 * 32; i += 128) {
        int vq = i >> 5, d = i & 31;
        qh[vq][d] = g_q[(size_t)(b * 64 + vq) * D_ + h * 32 + d];
        kh[vq][d] = g_k[(size_t)(b * 64 + vq) * D_ + h * 32 + d];
    }
    __syncthreads();

    const float scale = rsqrtf((float)DH_);
    for (int i = tid; i < 64 * 64; i += 128) {
        int vq = i >> 6, vk = i & 63;
        float s = 0.0f;
#pragma unroll
        for (int d = 0; d < 32; d++) s += qh[vq][d] * kh[vk][d];
        sc[vq][vk] = s * scale;
    }
    __syncthreads();

    if (tid < 64) {
        int vq = tid;
        float mx = -1e30f;
        for (int vk = 0; vk < 64; vk++) mx = fmaxf(mx, sc[vq][vk]);
        float sum = 0.0f;
        for (int vk = 0; vk < 64; vk++) { float e = expf(sc[vq][vk] - mx); sc[vq][vk] = e; sum += e; }
        float inv = 1.0f / sum;
        __nv_bfloat16* dst = g_attn + (size_t)((b * H_ + h) * 64 + vq) * 64;
        for (int vk = 0; vk < 64; vk++) dst[vk] = __float2bfloat16(sc[vq][vk] * inv);
    }
}

// ---------------- k_main helpers ---------------------------------------------
__device__ __forceinline__ void load_wchunk(__nv_bfloat16* sW,
                                            const __nv_bfloat16* __restrict__ Wg,
                                            int kc, int tid) {
#pragma unroll
    for (int i = 0; i < 4; i++) {
        int idx = tid + i * 512;            // 0..2047
        int n = idx >> 3, seg = idx & 7;
        cp16(sW + n * LDW + seg * 8, Wg + (size_t)n * 256 + kc * 64 + seg * 8);
    }
    cp_commit();
}

// C(128x256) = A(128x256 bf16 in sA) @ W(256x256)^T.
// Warp w = rb*4+cb... (rb = w>>2 rows 32, cb = w&3 cols 64). acc[2][8][4].
// Caller must have issued load_wchunk(sW0, Wg, 0) + commit already.
__device__ __forceinline__ void gemm_k256(const __nv_bfloat16* __restrict__ Wg,
                                          const __nv_bfloat16* sA,
                                          __nv_bfloat16* sW0, __nv_bfloat16* sW1,
                                          float acc[2][8][4], int tid, int lane) {
    int w = tid >> 5, rb = w >> 2, cb = w & 3;
#pragma unroll
    for (int i = 0; i < 2; i++)
#pragma unroll
        for (int j = 0; j < 8; j++)
#pragma unroll
            for (int e = 0; e < 4; e++) acc[i][j][e] = 0.0f;

    int arow = lane & 15, acolb = (lane >> 4) << 3;
    int brow = (lane & 7) + ((lane & 16) ? 8 : 0), bcolb = (lane & 8) ? 8 : 0;

#pragma unroll
    for (int kc = 0; kc < 4; kc++) {
        const __nv_bfloat16* cur = (kc & 1) ? sW1 : sW0;
        __nv_bfloat16* nxt = (kc & 1) ? sW0 : sW1;
        if (kc < 3) { load_wchunk(nxt, Wg, kc + 1, tid); cp_wait<1>(); }
        else        { cp_wait<0>(); }
        __syncthreads();
#pragma unroll
        for (int s = 0; s < 4; s++) {
            int k0 = s * 16;
            unsigned a0[4], a1[4];
            ldsm_x4(a0, sA + (rb * 32 + arow) * LDA + kc * 64 + k0 + acolb);
            ldsm_x4(a1, sA + (rb * 32 + 16 + arow) * LDA + kc * 64 + k0 + acolb);
#pragma unroll
            for (int jj = 0; jj < 4; jj++) {
                unsigned bb[4];
                ldsm_x4(bb, cur + (cb * 64 + jj * 16 + brow) * LDW + k0 + bcolb);
                mma_bf16(acc[0][jj * 2 + 0], a0, bb + 0);
                mma_bf16(acc[0][jj * 2 + 1], a0, bb + 2);
                mma_bf16(acc[1][jj * 2 + 0], a1, bb + 0);
                mma_bf16(acc[1][jj * 2 + 1], a1, bb + 2);
            }
        }
        __syncthreads();
    }
}

// convert f32 accumulators -> bf16 directly into sA (no f32 staging)
__device__ __forceinline__ void store_acc_bf16(float acc[2][8][4], __nv_bfloat16* sA,
                                               int tid, int lane) {
    int w = tid >> 5, rb = w >> 2, cb = w & 3;
    int r0 = rb * 32 + (lane >> 2), c0 = cb * 64 + (lane & 3) * 2;
#pragma unroll
    for (int i = 0; i < 2; i++)
#pragma unroll
        for (int jj = 0; jj < 8; jj++) {
            __nv_bfloat162 lo = __floats2bfloat162_rn(acc[i][jj][0], acc[i][jj][1]);
            __nv_bfloat162 hi = __floats2bfloat162_rn(acc[i][jj][2], acc[i][jj][3]);
            *(__nv_bfloat162*)(sA + (r0 + i * 16) * LDA + c0 + jj * 8) = lo;
            *(__nv_bfloat162*)(sA + (r0 + i * 16 + 8) * LDA + c0 + jj * 8) = hi;
        }
}

// ---------------- K5: fused LN + V-GEMM + attn-mix + proj + residual ---------
// One block per (b, t-pair): 128 rows (2 t) x 256 cols. 512 threads, raw mma.
__global__ void __launch_bounds__(512, 1)
k_main(const float* __restrict__ x, const float* __restrict__ lnw,
       const float* __restrict__ lnb, const float* __restrict__ bproj,
       float* __restrict__ out) {
    extern __shared__ char smem[];
    __nv_bfloat16* sA  = (__nv_bfloat16*)(smem + OFF_A);
    __nv_bfloat16* sW0 = (__nv_bfloat16*)(smem + OFF_W0);
    __nv_bfloat16* sW1 = (__nv_bfloat16*)(smem + OFF_W1);
    __nv_bfloat16* sAt = (__nv_bfloat16*)(smem + OFF_AT);   // [8*64][LDT]

    int b = blockIdx.x / 129, tp = blockIdx.x % 129;
    int t0 = tp * 2, t1 = min(t0 + 1, 256);
    int tid = threadIdx.x, w = tid >> 5, lane = tid & 31;

    // ---- kick off attn preload for this b (8 heads, repack stride LDT) ----
    {
        const __nv_bfloat16* src = g_attn + (size_t)b * 8 * 64 * 64;
        for (int i = tid; i < 4096; i += 512) {
            int hrow = i >> 3, seg = i & 7;
            cp16(sAt + hrow * LDT + seg * 8, src + i * 8);
        }
        cp_commit();
    }

    // ---- LayerNorm: 128 rows (r<64 -> t0, else t1) -> sA bf16 ----
    for (int r = w; r < 128; r += 16) {
        int t = (r < 64) ? t0 : t1;
        int v = r & 63;
        const float* row = x + ((size_t)(b * 64 + v) * T1_ + t) * D_;
        float rr[8];
#pragma unroll
        for (int j = 0; j < 8; j++) rr[j] = row[lane + 32 * j];
        float s = 0.0f;
#pragma unroll
        for (int j = 0; j < 8; j++) s += rr[j];
        s = warp_sum(s);
        float mu = s * (1.0f / 256.0f);
        float var = 0.0f;
#pragma unroll
        for (int j = 0; j < 8; j++) { float d = rr[j] - mu; var += d * d; }
        var = warp_sum(var);
        float rs = rsqrtf(var * (1.0f / 256.0f) + EPS);
#pragma unroll
        for (int j = 0; j < 8; j++) {
            int d = lane + 32 * j;
            sA[r * LDA + d] = __float2bfloat16((rr[j] - mu) * rs * lnw[d] + lnb[d]);
        }
    }

    // ---- vf = xn @ Wv^T (chunk0 issued here; gemm syncs internally) ----
    {
        float acc[2][8][4];
        load_wchunk(sW0, g_wb + (size_t)512 * 256, 0, tid);
        gemm_k256(g_wb + (size_t)512 * 256, sA, sW0, sW1, acc, tid, lane);
        // prefetch proj chunk0 while we convert + mix (sW0 is free now)
        load_wchunk(sW0, g_wp, 0, tid);
        store_acc_bf16(acc, sA, tid, lane);   // vf (bf16) into sA
    }
    __syncthreads();

    // ---- attn mixing: warp (tsub = w>>3, h = w&7) owns tile [tsub*64..][h*32..]
    {
        int tsub = w >> 3, h = w & 7;
        float mc[4][4][4];
#pragma unroll
        for (int a = 0; a < 4; a++)
#pragma unroll
            for (int c = 0; c < 4; c++)
#pragma unroll
                for (int e = 0; e < 4; e++) mc[a][c][e] = 0.0f;

        int arow = lane & 15, acolb = (lane >> 4) << 3;
        int trow = (lane & 7) + ((lane & 8) ? 8 : 0), tcolb = (lane & 16) ? 8 : 0;
        const __nv_bfloat16* at = sAt + h * 64 * LDT;
#pragma unroll
        for (int k = 0; k < 4; k++) {
            int k0 = k * 16;
            unsigned bb0[4], bb1[4];
            ldsm_x4t(bb0, sA + (tsub * 64 + k0 + trow) * LDA + h * 32 + tcolb);
            ldsm_x4t(bb1, sA + (tsub * 64 + k0 + trow) * LDA + h * 32 + 16 + tcolb);
#pragma unroll
            for (int rt = 0; rt < 4; rt++) {
                unsigned aa[4];
                ldsm_x4(aa, at + (rt * 16 + arow) * LDT + k0 + acolb);
                mma_bf16(mc[rt][0], aa, bb0 + 0);
                mma_bf16(mc[rt][1], aa, bb0 + 2);
                mma_bf16(mc[rt][2], aa, bb1 + 0);
                mma_bf16(mc[rt][3], aa, bb1 + 2);
            }
        }
        // per-warp tile is self-contained: safe to overwrite own region
        int r0 = tsub * 64 + (lane >> 2), c0 = h * 32 + (lane & 3) * 2;
#pragma unroll
        for (int rt = 0; rt < 4; rt++)
#pragma unroll
            for (int jj = 0; jj < 4; jj++) {
                __nv_bfloat162 lo = __floats2bfloat162_rn(mc[rt][jj][0], mc[rt][jj][1]);
                __nv_bfloat162 hi = __floats2bfloat162_rn(mc[rt][jj][2], mc[rt][jj][3]);
                *(__nv_bfloat162*)(sA + (r0 + rt * 16) * LDA + c0 + jj * 8) = lo;
                *(__nv_bfloat162*)(sA + (r0 + rt * 16 + 8) * LDA + c0 + jj * 8) = hi;
            }
    }
    __syncthreads();

    // ---- proj = mixed @ Wp^T, epilogue straight from registers ----
    {
        float acc[2][8][4];
        gemm_k256(g_wp, sA, sW0, sW1, acc, tid, lane);

        int rb = w >> 2, cb = w & 3;
        bool dup = (t1 == t0);
        if (!(rb >= 2 && dup)) {
            int r0 = rb * 32 + (lane >> 2), c0 = cb * 64 + (lane & 3) * 2;
            float2 biasv[8];
#pragma unroll
            for (int jj = 0; jj < 8; jj++) {
                biasv[jj].x = bproj[c0 + jj * 8];
                biasv[jj].y = bproj[c0 + jj * 8 + 1];
            }
#pragma unroll
            for (int i = 0; i < 2; i++)
#pragma unroll
                for (int half = 0; half < 2; half++) {
                    int rr = r0 + i * 16 + half * 8;
                    int v = rr & 63;
                    int t = (rr < 64) ? t0 : t1;
                    size_t base = ((size_t)(b * 64 + v) * T1_ + t) * D_;
#pragma unroll
                    for (int jj = 0; jj < 8; jj++) {
                        size_t gi = base + c0 + jj * 8;
                        float2 xv = *(const float2*)(x + gi);
                        float2 o;
                        o.x = acc[i][jj][half * 2 + 0] + biasv[jj].x + xv.x;
                        o.y = acc[i][jj][half * 2 + 1] + biasv[jj].y + xv.y;
                        *(float2*)(out + gi) = o;
                    }
                }
        }
    }
}

// ---------------- launch ----------------------------------------------------
extern "C" void kernel_launch(void* const* d_in, const int* in_sizes, int n_in,
                              void* d_out, int out_size) {
    const float* x     = (const float*)d_in[0];
    const void*  mask  = d_in[1];
    const float* lnw   = (const float*)d_in[2];
    const float* lnb   = (const float*)d_in[3];
    const float* wqkv  = (const float*)d_in[4];
    const float* wproj = (const float*)d_in[5];
    const float* bproj = (const float*)d_in[6];
    float* out = (float*)d_out;

    cudaFuncSetAttribute(k_main, cudaFuncAttributeMaxDynamicSharedMemorySize, SM_MAIN);
    cudaFuncSetAttribute(k_qk, cudaFuncAttributeMaxDynamicSharedMemorySize, SM_QK);

    k_detect<<<1, 256>>>((const unsigned char*)mask);
    k_convert<<<1024, 256>>>(wqkv, wproj);
    k_xbar<<<B_ * V_, 256>>>(x, mask, lnw, lnb);
    k_qk<<<64, 256, SM_QK>>>();
    k_attn<<<B_ * H_, 128>>>();
    k_main<<<B_ * 129, 512, SM_MAIN>>>(x, lnw, lnb, bproj, out);
}